// round 5
// baseline (speedup 1.0000x reference)
#include <cuda_runtime.h>
#include <math.h>

#define NEXP 4
#define BATCH 16
#define CIN 3
#define HIMG 256
#define WIMG 256
#define HW 65536
#define DTOT 196608
#define HID 64

// ---------------- device scratch (no allocations allowed) ----------------
__device__ float g_tgate[BATCH][CIN][NEXP];   // sum_hw x[b,c,:]*w_gate[(c,:),e]
__device__ float g_tnoise[BATCH][CIN][NEXP];  // same for w_noise
__device__ float g_refsum[BATCH][CIN];        // sum_hw ref[b,c,:]
__device__ float g_gateval[BATCH][2];         // top-2 gate values
__device__ int   g_topidx[BATCH][2];          // top-2 expert indices

__global__ void k_zero_scratch() {
    int t = threadIdx.x;
    if (t < BATCH * CIN * NEXP) {
        ((float*)g_tgate)[t]  = 0.f;
        ((float*)g_tnoise)[t] = 0.f;
    }
    if (t < BATCH * CIN) ((float*)g_refsum)[t] = 0.f;
}

__device__ __forceinline__ float warp_sum(float v) {
    #pragma unroll
    for (int o = 16; o > 0; o >>= 1) v += __shfl_down_sync(0xffffffffu, v, o);
    return v;
}

// ---------------- K1: per-(b,c) partial reductions ----------------
// grid (BATCH*CIN, 16 chunks), 256 threads
__global__ void k_partials(const float* __restrict__ x, const float* __restrict__ ref,
                           const float* __restrict__ wg, const float* __restrict__ wn) {
    int bc = blockIdx.x;
    int b = bc / CIN, c = bc - b * CIN;
    int base = blockIdx.y * 4096;
    const float*  xp  = x   + (size_t)b * DTOT + (size_t)c * HW + base;
    const float*  rp  = ref + (size_t)b * DTOT + (size_t)c * HW + base;
    const float4* wgp = (const float4*)wg + (size_t)c * HW + base; // row d = one float4
    const float4* wnp = (const float4*)wn + (size_t)c * HW + base;

    float ag[4] = {0,0,0,0}, an[4] = {0,0,0,0}, ar = 0.f;
    for (int i = threadIdx.x; i < 4096; i += 256) {
        float xv = xp[i], rv = rp[i];
        float4 g4 = wgp[i], n4 = wnp[i];
        ag[0] += xv * g4.x; ag[1] += xv * g4.y; ag[2] += xv * g4.z; ag[3] += xv * g4.w;
        an[0] += xv * n4.x; an[1] += xv * n4.y; an[2] += xv * n4.z; an[3] += xv * n4.w;
        ar += rv;
    }
    int lane = threadIdx.x & 31;
    #pragma unroll
    for (int e = 0; e < 4; e++) {
        float s = warp_sum(ag[e]);
        if (lane == 0) atomicAdd(&g_tgate[b][c][e], s);
        s = warp_sum(an[e]);
        if (lane == 0) atomicAdd(&g_tnoise[b][c][e], s);
    }
    float s = warp_sum(ar);
    if (lane == 0) atomicAdd(&g_refsum[b][c], s);
}

// ---------------- K2: tiny gating kernel (1 block, 16 threads) ----------------
// FFT branch collapsed to DC term: mean(irfft2_ortho(X)) = Re(X[0,0]) / 256
__global__ void k_gate(const float* __restrict__ noise,
                       const float* __restrict__ mw1, const float* __restrict__ mb1,
                       const float* __restrict__ mw2, const float* __restrict__ mb2,
                       const float* __restrict__ ehw, const float* __restrict__ ehb,
                       const float* __restrict__ fre,
                       float* __restrict__ out, int out_size) {
    __shared__ float sg[BATCH][NEXP];
    __shared__ float spb[BATCH][NEXP];
    int b = threadIdx.x;
    if (b < BATCH) {
        float s[CIN];
        #pragma unroll
        for (int c = 0; c < CIN; c++) s[c] = g_refsum[b][c] * (1.f / 256.f);

        // pooled at DC = [s0,s1,s2,0,0,0,s0,s1,s2,0,0,0]
        float m1[6];
        #pragma unroll
        for (int o = 0; o < 6; o++) {
            float a = mb1[o];
            #pragma unroll
            for (int c = 0; c < 3; c++) a += (mw1[o*12 + c] + mw1[o*12 + 6 + c]) * s[c];
            m1[o] = fmaxf(a, 0.f);
        }
        float m2[6];
        #pragma unroll
        for (int o = 0; o < 6; o++) {
            float a = mb2[o];
            #pragma unroll
            for (int i = 0; i < 6; i++) a += mw2[o*6 + i] * m1[i];
            m2[o] = a;
        }
        float e0[6];
        #pragma unroll
        for (int o = 0; o < 6; o++) e0[o] = m2[o] * fre[(size_t)o * HIMG * (WIMG/2 + 1)];
        float eh[6];
        #pragma unroll
        for (int o = 0; o < 6; o++) {
            float a = ehb[o];
            #pragma unroll
            for (int i = 0; i < 6; i++) a += ehw[o*6 + i] * e0[i];
            eh[o] = fmaxf(a, 0.f);
        }
        // spatial mean -> channel softmax
        float lg0 = eh[0] * (1.f/256.f), lg1 = eh[1] * (1.f/256.f), lg2 = eh[2] * (1.f/256.f);
        float mx = fmaxf(lg0, fmaxf(lg1, lg2));
        float ex0 = expf(lg0 - mx), ex1 = expf(lg1 - mx), ex2 = expf(lg2 - mx);
        float inv = 1.f / (ex0 + ex1 + ex2);
        float p[3] = {ex0 * inv, ex1 * inv, ex2 * inv};

        float cl[4], rn[4];
        #pragma unroll
        for (int e = 0; e < 4; e++) {
            float a = 0.f, bn = 0.f;
            #pragma unroll
            for (int c = 0; c < 3; c++) {
                float f = 1.f + p[c];
                a  += f * g_tgate[b][c][e];
                bn += f * g_tnoise[b][c][e];
            }
            cl[e] = a; rn[e] = bn;
        }
        float sd[4], nz[4];
        #pragma unroll
        for (int e = 0; e < 4; e++) {
            float r = rn[e];
            float sp = fmaxf(r, 0.f) + log1pf(expf(-fabsf(r)));  // stable softplus
            sd[e] = sp + 0.01f;
            nz[e] = cl[e] + noise[b*4 + e] * sd[e];
        }
        // top-3 (stable selection sort, matches lax.top_k tie order)
        float v[4]; int id[4];
        #pragma unroll
        for (int e = 0; e < 4; e++) { v[e] = nz[e]; id[e] = e; }
        #pragma unroll
        for (int s0 = 0; s0 < 3; s0++) {
            int best = s0;
            #pragma unroll
            for (int j = 0; j < 4; j++)
                if (j > s0 && v[j] > v[best]) best = j;
            float tv = v[s0]; v[s0] = v[best]; v[best] = tv;
            int   ti = id[s0]; id[s0] = id[best]; id[best] = ti;
        }
        float eA = expf(v[1] - v[0]);
        float g0 = 1.f / (1.f + eA), g1 = eA / (1.f + eA);
        g_gateval[b][0] = g0; g_gateval[b][1] = g1;
        g_topidx[b][0] = id[0]; g_topidx[b][1] = id[1];

        float gt[4] = {0,0,0,0};
        gt[id[0]] = g0; gt[id[1]] = g1;
        float thrin = v[2], throut = v[1];
        #pragma unroll
        for (int e = 0; e < 4; e++) {
            sg[b][e] = gt[e];
            float t = (nz[e] > thrin) ? (cl[e] - thrin) / sd[e] : (cl[e] - throut) / sd[e];
            spb[b][e] = normcdff(t);
        }
    }
    __syncthreads();
    if (threadIdx.x == 0) {
        float imp[4] = {0,0,0,0}, ld[4] = {0,0,0,0};
        for (int bb = 0; bb < BATCH; bb++)
            for (int e = 0; e < 4; e++) { imp[e] += sg[bb][e]; ld[e] += spb[bb][e]; }
        float loss = 0.f;
        #pragma unroll
        for (int which = 0; which < 2; which++) {
            float* vv = which ? ld : imp;
            float m = (vv[0] + vv[1] + vv[2] + vv[3]) * 0.25f;
            float va = 0.f;
            for (int e = 0; e < 4; e++) { float d = vv[e] - m; va += d * d; }
            va *= (1.f / 3.f);  // ddof=1
            loss += va / (m * m + 1e-10f);
        }
        loss *= 0.01f;
        if (out_size > BATCH * HW) out[out_size - 1] = loss;
    }
}

// ---------------- K3: fused sparse expert convs ----------------
// grid (8,8,BATCH), 256 threads; 32x32 output tile; per block: 2 experts (top-2)
__global__ void __launch_bounds__(256, 2)
k_expert(const float* __restrict__ x,
         const float* __restrict__ ew1, const float* __restrict__ eb1,
         const float* __restrict__ ew2, const float* __restrict__ eb2,
         float* __restrict__ out) {
    __shared__ float xs[3*1296 + 8];     // 3 x 36x36 (halo 2), +pad for harmless over-read
    __shared__ float hs[2][34*36];       // 2 h-channels, 34x34 (halo 1), stride 36
    __shared__ float w1s[2][HID*27];
    __shared__ float b1s[2][HID];
    __shared__ float w2s[2][HID*9];      // pre-scaled by gate value

    int tid = threadIdx.x;
    int b = blockIdx.z;
    int row0 = blockIdx.y * 32, col0 = blockIdx.x * 32;
    int i0 = g_topidx[b][0], i1 = g_topidx[b][1];
    float ga = g_gateval[b][0], gb = g_gateval[b][1];

    for (int t = tid; t < HID*27; t += 256) {
        w1s[0][t] = ew1[i0*HID*27 + t];
        w1s[1][t] = ew1[i1*HID*27 + t];
    }
    for (int t = tid; t < HID*9; t += 256) {
        w2s[0][t] = ga * ew2[i0*HID*9 + t];
        w2s[1][t] = gb * ew2[i1*HID*9 + t];
    }
    if (tid < HID) {
        b1s[0][tid] = eb1[i0*HID + tid];
        b1s[1][tid] = eb1[i1*HID + tid];
    }
    for (int t = tid; t < 3*1296; t += 256) {
        int ci = t / 1296;
        int rem = t - ci * 1296;
        int r = rem / 36, cc = rem - r * 36;
        int gr = row0 - 2 + r, gc = col0 - 2 + cc;
        float v = 0.f;
        if (gr >= 0 && gr < HIMG && gc >= 0 && gc < WIMG)
            v = x[((size_t)b * CIN + ci) * HW + gr * WIMG + gc];
        xs[t] = v;
    }
    __syncthreads();

    float bias2 = ga * eb2[i0] + gb * eb2[i1];
    float acc[4] = {bias2, bias2, bias2, bias2};
    int tx = tid & 31, ty4 = (tid >> 5) * 4;

    #pragma unroll 1
    for (int k = 0; k < 2; k++) {
        #pragma unroll 1
        for (int hc = 0; hc < HID; hc += 2) {
            // ---- conv1 for 2 channels into hs (x LDS shared across channels) ----
            float wr0[27], wr1[27];
            #pragma unroll
            for (int j = 0; j < 27; j++) {
                wr0[j] = w1s[k][hc*27 + j];
                wr1[j] = w1s[k][hc*27 + 27 + j];
            }
            float bb0 = b1s[k][hc], bb1 = b1s[k][hc + 1];
            for (int t = tid; t < 306; t += 256) {   // 34 rows x 9 col-groups-of-4
                int r  = t / 9;
                int c0 = (t - r * 9) * 4;
                float h0[4] = {bb0, bb0, bb0, bb0};
                float h1[4] = {bb1, bb1, bb1, bb1};
                #pragma unroll
                for (int ci = 0; ci < 3; ci++) {
                    #pragma unroll
                    for (int dr = 0; dr < 3; dr++) {
                        const float* xr = &xs[ci*1296 + (r + dr)*36 + c0];
                        float x0 = xr[0], x1 = xr[1], x2 = xr[2],
                              x3 = xr[3], x4 = xr[4], x5 = xr[5];
                        int wb = ci*9 + dr*3;
                        float a0 = wr0[wb], a1 = wr0[wb+1], a2 = wr0[wb+2];
                        h0[0] += a0*x0 + a1*x1 + a2*x2;
                        h0[1] += a0*x1 + a1*x2 + a2*x3;
                        h0[2] += a0*x2 + a1*x3 + a2*x4;
                        h0[3] += a0*x3 + a1*x4 + a2*x5;
                        float d0 = wr1[wb], d1 = wr1[wb+1], d2 = wr1[wb+2];
                        h1[0] += d0*x0 + d1*x1 + d2*x2;
                        h1[1] += d0*x1 + d1*x2 + d2*x3;
                        h1[2] += d0*x2 + d1*x3 + d2*x4;
                        h1[3] += d0*x3 + d1*x4 + d2*x5;
                    }
                }
                int ghr = row0 - 1 + r;
                bool rok = (ghr >= 0) && (ghr < HIMG);
                #pragma unroll
                for (int j = 0; j < 4; j++) {
                    int cc = c0 + j;
                    if (cc < 34) {
                        int ghc = col0 - 1 + cc;
                        bool ok = rok && (ghc >= 0) && (ghc < WIMG);
                        hs[0][r*36 + cc] = ok ? fmaxf(h0[j], 0.f) : 0.f; // conv2 sees zero pad
                        hs[1][r*36 + cc] = ok ? fmaxf(h1[j], 0.f) : 0.f;
                    }
                }
            }
            __syncthreads();
            // ---- conv2 accumulate (gate already folded into w2s) ----
            #pragma unroll
            for (int ch = 0; ch < 2; ch++) {
                float wq[9];
                #pragma unroll
                for (int j = 0; j < 9; j++) wq[j] = w2s[k][(hc + ch)*9 + j];
                float hv[6][3];
                #pragma unroll
                for (int rrow = 0; rrow < 6; rrow++) {
                    const float* hp = &hs[ch][(ty4 + rrow)*36 + tx];
                    hv[rrow][0] = hp[0]; hv[rrow][1] = hp[1]; hv[rrow][2] = hp[2];
                }
                #pragma unroll
                for (int rr = 0; rr < 4; rr++) {
                    float a = 0.f;
                    #pragma unroll
                    for (int dr = 0; dr < 3; dr++)
                        #pragma unroll
                        for (int dc = 0; dc < 3; dc++)
                            a += wq[dr*3 + dc] * hv[rr + dr][dc];
                    acc[rr] += a;
                }
            }
            __syncthreads();
        }
    }
    #pragma unroll
    for (int rr = 0; rr < 4; rr++)
        out[(size_t)b * HW + (row0 + ty4 + rr) * WIMG + col0 + tx] = acc[rr];
}

// ---------------- launch ----------------
extern "C" void kernel_launch(void* const* d_in, const int* in_sizes, int n_in,
                              void* d_out, int out_size) {
    const float* x     = (const float*)d_in[0];
    const float* ref   = (const float*)d_in[1];
    const float* noise = (const float*)d_in[2];
    const float* mw1   = (const float*)d_in[3];
    const float* mb1   = (const float*)d_in[4];
    const float* mw2   = (const float*)d_in[5];
    const float* mb2   = (const float*)d_in[6];
    const float* ehw   = (const float*)d_in[7];
    const float* ehb   = (const float*)d_in[8];
    const float* fre   = (const float*)d_in[9];
    const float* wg    = (const float*)d_in[10];
    const float* wn    = (const float*)d_in[11];
    const float* ew1   = (const float*)d_in[12];
    const float* eb1   = (const float*)d_in[13];
    const float* ew2   = (const float*)d_in[14];
    const float* eb2   = (const float*)d_in[15];
    float* out = (float*)d_out;

    k_zero_scratch<<<1, 256>>>();
    k_partials<<<dim3(BATCH * CIN, 16), 256>>>(x, ref, wg, wn);
    k_gate<<<1, 16>>>(noise, mw1, mb1, mw2, mb2, ehw, ehb, fre, out, out_size);
    k_expert<<<dim3(8, 8, BATCH), 256>>>(x, ew1, eb1, ew2, eb2, out);
}

// round 9
// speedup vs baseline: 1.4887x; 1.4887x over previous
#include <cuda_runtime.h>
#include <math.h>

#define NEXP 4
#define BATCH 16
#define CIN 3
#define HIMG 256
#define WIMG 256
#define HW 65536
#define DTOT 196608
#define HID 64

// expert-conv tile geometry
#define TW 64
#define TH 32
#define XSW 68                 // xs row stride (floats); cols col0-2 .. col0+65
#define XSH 36                 // rows row0-2 .. row0+33
#define HSW 68                 // hs cols (float2), hc in [0,68), valid [0,66)
#define HSH 34                 // hr in [0,34)
#define SM_XS 0
#define SM_HS (3*XSH*XSW)      // 7344 floats
#define SMEM_FLOATS (SM_HS + 2*HSH*HSW + 8)   // 11976 floats = 47904 B

// ---------------- device scratch (no allocations allowed) ----------------
__device__ float g_tgate[BATCH][CIN][NEXP];
__device__ float g_tnoise[BATCH][CIN][NEXP];
__device__ float g_refsum[BATCH][CIN];
__device__ float g_gateval[BATCH][2];
__device__ int   g_topidx[BATCH][2];

__global__ void k_zero_scratch() {
    int t = threadIdx.x;
    if (t < BATCH * CIN * NEXP) {
        ((float*)g_tgate)[t]  = 0.f;
        ((float*)g_tnoise)[t] = 0.f;
    }
    if (t < BATCH * CIN) ((float*)g_refsum)[t] = 0.f;
}

__device__ __forceinline__ float warp_sum(float v) {
    #pragma unroll
    for (int o = 16; o > 0; o >>= 1) v += __shfl_down_sync(0xffffffffu, v, o);
    return v;
}

// ---------------- K1: per-(b,c) partial reductions ----------------
__global__ void k_partials(const float* __restrict__ x, const float* __restrict__ ref,
                           const float* __restrict__ wg, const float* __restrict__ wn) {
    int bc = blockIdx.x;
    int b = bc / CIN, c = bc - b * CIN;
    int base = blockIdx.y * 4096;
    const float*  xp  = x   + (size_t)b * DTOT + (size_t)c * HW + base;
    const float*  rp  = ref + (size_t)b * DTOT + (size_t)c * HW + base;
    const float4* wgp = (const float4*)wg + (size_t)c * HW + base;
    const float4* wnp = (const float4*)wn + (size_t)c * HW + base;

    float ag[4] = {0,0,0,0}, an[4] = {0,0,0,0}, ar = 0.f;
    for (int i = threadIdx.x; i < 4096; i += 256) {
        float xv = xp[i], rv = rp[i];
        float4 g4 = wgp[i], n4 = wnp[i];
        ag[0] += xv * g4.x; ag[1] += xv * g4.y; ag[2] += xv * g4.z; ag[3] += xv * g4.w;
        an[0] += xv * n4.x; an[1] += xv * n4.y; an[2] += xv * n4.z; an[3] += xv * n4.w;
        ar += rv;
    }
    int lane = threadIdx.x & 31;
    #pragma unroll
    for (int e = 0; e < 4; e++) {
        float s = warp_sum(ag[e]);
        if (lane == 0) atomicAdd(&g_tgate[b][c][e], s);
        s = warp_sum(an[e]);
        if (lane == 0) atomicAdd(&g_tnoise[b][c][e], s);
    }
    float s = warp_sum(ar);
    if (lane == 0) atomicAdd(&g_refsum[b][c], s);
}

// ---------------- K2: tiny gating kernel ----------------
// FFT branch collapsed to DC term: mean(irfft2_ortho(X)) = Re(X[0,0]) / 256
__global__ void k_gate(const float* __restrict__ noise,
                       const float* __restrict__ mw1, const float* __restrict__ mb1,
                       const float* __restrict__ mw2, const float* __restrict__ mb2,
                       const float* __restrict__ ehw, const float* __restrict__ ehb,
                       const float* __restrict__ fre,
                       float* __restrict__ out, int out_size) {
    __shared__ float sg[BATCH][NEXP];
    __shared__ float spb[BATCH][NEXP];
    int b = threadIdx.x;
    if (b < BATCH) {
        float s[CIN];
        #pragma unroll
        for (int c = 0; c < CIN; c++) s[c] = g_refsum[b][c] * (1.f / 256.f);

        float m1[6];
        #pragma unroll
        for (int o = 0; o < 6; o++) {
            float a = mb1[o];
            #pragma unroll
            for (int c = 0; c < 3; c++) a += (mw1[o*12 + c] + mw1[o*12 + 6 + c]) * s[c];
            m1[o] = fmaxf(a, 0.f);
        }
        float m2[6];
        #pragma unroll
        for (int o = 0; o < 6; o++) {
            float a = mb2[o];
            #pragma unroll
            for (int i = 0; i < 6; i++) a += mw2[o*6 + i] * m1[i];
            m2[o] = a;
        }
        float e0[6];
        #pragma unroll
        for (int o = 0; o < 6; o++) e0[o] = m2[o] * fre[(size_t)o * HIMG * (WIMG/2 + 1)];
        float eh[6];
        #pragma unroll
        for (int o = 0; o < 6; o++) {
            float a = ehb[o];
            #pragma unroll
            for (int i = 0; i < 6; i++) a += ehw[o*6 + i] * e0[i];
            eh[o] = fmaxf(a, 0.f);
        }
        float lg0 = eh[0] * (1.f/256.f), lg1 = eh[1] * (1.f/256.f), lg2 = eh[2] * (1.f/256.f);
        float mx = fmaxf(lg0, fmaxf(lg1, lg2));
        float ex0 = expf(lg0 - mx), ex1 = expf(lg1 - mx), ex2 = expf(lg2 - mx);
        float inv = 1.f / (ex0 + ex1 + ex2);
        float p[3] = {ex0 * inv, ex1 * inv, ex2 * inv};

        float cl[4], rn[4];
        #pragma unroll
        for (int e = 0; e < 4; e++) {
            float a = 0.f, bn = 0.f;
            #pragma unroll
            for (int c = 0; c < 3; c++) {
                float f = 1.f + p[c];
                a  += f * g_tgate[b][c][e];
                bn += f * g_tnoise[b][c][e];
            }
            cl[e] = a; rn[e] = bn;
        }
        float sd[4], nz[4];
        #pragma unroll
        for (int e = 0; e < 4; e++) {
            float r = rn[e];
            float sp = fmaxf(r, 0.f) + log1pf(expf(-fabsf(r)));
            sd[e] = sp + 0.01f;
            nz[e] = cl[e] + noise[b*4 + e] * sd[e];
        }
        float v[4]; int id[4];
        #pragma unroll
        for (int e = 0; e < 4; e++) { v[e] = nz[e]; id[e] = e; }
        #pragma unroll
        for (int s0 = 0; s0 < 3; s0++) {
            int best = s0;
            #pragma unroll
            for (int j = 0; j < 4; j++)
                if (j > s0 && v[j] > v[best]) best = j;
            float tv = v[s0]; v[s0] = v[best]; v[best] = tv;
            int   ti = id[s0]; id[s0] = id[best]; id[best] = ti;
        }
        float eA = expf(v[1] - v[0]);
        float g0 = 1.f / (1.f + eA), g1 = eA / (1.f + eA);
        g_gateval[b][0] = g0; g_gateval[b][1] = g1;
        g_topidx[b][0] = id[0]; g_topidx[b][1] = id[1];

        float gt[4] = {0,0,0,0};
        gt[id[0]] = g0; gt[id[1]] = g1;
        float thrin = v[2], throut = v[1];
        #pragma unroll
        for (int e = 0; e < 4; e++) {
            sg[b][e] = gt[e];
            float t = (nz[e] > thrin) ? (cl[e] - thrin) / sd[e] : (cl[e] - throut) / sd[e];
            spb[b][e] = normcdff(t);
        }
    }
    __syncthreads();
    if (threadIdx.x == 0) {
        float imp[4] = {0,0,0,0}, ld[4] = {0,0,0,0};
        for (int bb = 0; bb < BATCH; bb++)
            for (int e = 0; e < 4; e++) { imp[e] += sg[bb][e]; ld[e] += spb[bb][e]; }
        float loss = 0.f;
        #pragma unroll
        for (int which = 0; which < 2; which++) {
            float* vv = which ? ld : imp;
            float m = (vv[0] + vv[1] + vv[2] + vv[3]) * 0.25f;
            float va = 0.f;
            for (int e = 0; e < 4; e++) { float d = vv[e] - m; va += d * d; }
            va *= (1.f / 3.f);
            loss += va / (m * m + 1e-10f);
        }
        loss *= 0.01f;
        if (out_size > BATCH * HW) out[out_size - 1] = loss;
    }
}

// ---------------- K3: fused sparse expert convs (v2.1) ----------------
// grid (4, 8, BATCH), 256 threads; 64x32 output tile; 2 experts (top-2).
// conv1: 2 channels/pass, tasks = 2 rows x 4 cols over h region 34x68,
//        x read from SMEM as aligned float4+float2 (conflict-free),
//        weights via __ldg float2 broadcast (off the SMEM crossbar).
// conv2: hs packed float2 (2ch), tasks = 4-row column strips, lane = column
//        (conflict-free), accumulators held in registers across all passes.
__global__ void __launch_bounds__(256, 2)
k_expert(const float* __restrict__ x,
         const float* __restrict__ ew1, const float* __restrict__ eb1,
         const float* __restrict__ ew2, const float* __restrict__ eb2,
         float* __restrict__ out) {
    __shared__ float sm[SMEM_FLOATS];
    float*  xs = sm + SM_XS;               // [3][36][68]
    float2* hs = (float2*)(sm + SM_HS);    // [34][68]

    int tid = threadIdx.x;
    int b = blockIdx.z;
    int row0 = blockIdx.y * TH, col0 = blockIdx.x * TW;
    int ie[2]   = {g_topidx[b][0], g_topidx[b][1]};
    float gv[2] = {g_gateval[b][0], g_gateval[b][1]};

    // ---- load x tile with halo 2 ----
    for (int t = tid; t < 3*XSH*XSW; t += 256) {
        int ci  = t / (XSH*XSW);
        int rem = t - ci*(XSH*XSW);
        int r = rem / XSW, c = rem - r*XSW;
        int gr = row0 - 2 + r, gc = col0 - 2 + c;
        float v = 0.f;
        if (gr >= 0 && gr < HIMG && gc >= 0 && gc < WIMG)
            v = x[((size_t)b*CIN + ci)*HW + gr*WIMG + gc];
        xs[t] = v;
    }
    __syncthreads();

    float bias2 = gv[0]*__ldg(&eb2[ie[0]]) + gv[1]*__ldg(&eb2[ie[1]]);
    float acc2[2][4];
    #pragma unroll
    for (int it = 0; it < 2; it++)
        #pragma unroll
        for (int rr = 0; rr < 4; rr++) acc2[it][rr] = 0.f;

    #pragma unroll 1
    for (int k = 0; k < 2; k++) {
        const float* w1base = ew1 + (size_t)ie[k] * (HID*27);
        const float* w2base = ew2 + (size_t)ie[k] * (HID*9);
        const float* b1base = eb1 + ie[k] * HID;
        float gk = gv[k];

        #pragma unroll 1
        for (int c0 = 0; c0 < HID; c0 += 2) {
            // ---- weights for 2 channels into registers (global float2 broadcast;
            //      c0 even -> offset c0*27 floats is 8B-aligned) ----
            float w1r[54];
            {
                const float2* wp = (const float2*)(w1base + c0*27);
                #pragma unroll
                for (int j = 0; j < 27; j++) {
                    float2 wv = __ldg(wp + j);
                    w1r[2*j] = wv.x; w1r[2*j+1] = wv.y;
                }
            }
            float bb0 = __ldg(b1base + c0), bb1 = __ldg(b1base + c0 + 1);

            // ---- conv1: h region 34 rows x 68 cols, tasks 2r x 4c (289) ----
            #pragma unroll 1
            for (int t = tid; t < 17*17; t += 256) {
                int trg = t / 17, tcg = t - trg*17;
                int hr0 = 2*trg, hc0 = 4*tcg;
                float a0[2][4], a1[2][4];
                #pragma unroll
                for (int o = 0; o < 2; o++)
                    #pragma unroll
                    for (int j = 0; j < 4; j++) { a0[o][j] = bb0; a1[o][j] = bb1; }

                #pragma unroll
                for (int ci = 0; ci < 3; ci++) {
                    const float* bp = xs + ci*(XSH*XSW) + hr0*XSW + hc0;
                    #pragma unroll
                    for (int xr = 0; xr < 4; xr++) {
                        float4 v4 = *(const float4*)(bp + xr*XSW);
                        float2 v2 = *(const float2*)(bp + xr*XSW + 4);
                        float xv0=v4.x, xv1=v4.y, xv2=v4.z,
                              xv3=v4.w, xv4=v2.x, xv5=v2.y;
                        #pragma unroll
                        for (int dr = 0; dr < 3; dr++) {
                            int o = xr - dr;
                            if (o == 0 || o == 1) {
                                float wA0 = w1r[ci*9 + dr*3 + 0];
                                float wA1 = w1r[ci*9 + dr*3 + 1];
                                float wA2 = w1r[ci*9 + dr*3 + 2];
                                a0[o][0] += wA0*xv0 + wA1*xv1 + wA2*xv2;
                                a0[o][1] += wA0*xv1 + wA1*xv2 + wA2*xv3;
                                a0[o][2] += wA0*xv2 + wA1*xv3 + wA2*xv4;
                                a0[o][3] += wA0*xv3 + wA1*xv4 + wA2*xv5;
                                float wB0 = w1r[27 + ci*9 + dr*3 + 0];
                                float wB1 = w1r[27 + ci*9 + dr*3 + 1];
                                float wB2 = w1r[27 + ci*9 + dr*3 + 2];
                                a1[o][0] += wB0*xv0 + wB1*xv1 + wB2*xv2;
                                a1[o][1] += wB0*xv1 + wB1*xv2 + wB2*xv3;
                                a1[o][2] += wB0*xv2 + wB1*xv3 + wB2*xv4;
                                a1[o][3] += wB0*xv3 + wB1*xv4 + wB2*xv5;
                            }
                        }
                    }
                }
                // store with image-boundary zero mask (conv2 sees zero padding)
                #pragma unroll
                for (int o = 0; o < 2; o++) {
                    int hr = hr0 + o;
                    int gr = row0 - 1 + hr;
                    bool rok = (gr >= 0) && (gr < HIMG);
                    #pragma unroll
                    for (int j = 0; j < 4; j++) {
                        int hc = hc0 + j;
                        int gc = col0 - 1 + hc;
                        bool ok = rok && (gc >= 0) && (gc < WIMG);
                        float2 hv;
                        hv.x = ok ? fmaxf(a0[o][j], 0.f) : 0.f;
                        hv.y = ok ? fmaxf(a1[o][j], 0.f) : 0.f;
                        hs[hr*HSW + hc] = hv;
                    }
                }
            }
            __syncthreads();

            // ---- conv2: accumulate (gate folded into weights) ----
            float wq0[9], wq1[9];
            {
                const float2* wp = (const float2*)(w2base + c0*9);  // c0 even -> 8B aligned
                float wtmp[18];
                #pragma unroll
                for (int j = 0; j < 9; j++) {
                    float2 wv = __ldg(wp + j);
                    wtmp[2*j] = wv.x; wtmp[2*j+1] = wv.y;
                }
                #pragma unroll
                for (int j = 0; j < 9; j++) {
                    wq0[j] = gk * wtmp[j];
                    wq1[j] = gk * wtmp[9 + j];
                }
            }
            #pragma unroll
            for (int it = 0; it < 2; it++) {
                int t = tid + it*256;
                int trg = t >> 6, c = t & 63;      // 8 row-groups x 64 cols
                const float2* hp = hs + (4*trg)*HSW + c;
                float2 h2[6][3];
                #pragma unroll
                for (int r6 = 0; r6 < 6; r6++)
                    #pragma unroll
                    for (int dc = 0; dc < 3; dc++)
                        h2[r6][dc] = hp[r6*HSW + dc];
                #pragma unroll
                for (int rr = 0; rr < 4; rr++) {
                    float a = 0.f;
                    #pragma unroll
                    for (int dr = 0; dr < 3; dr++)
                        #pragma unroll
                        for (int dc = 0; dc < 3; dc++) {
                            a += wq0[dr*3+dc] * h2[rr+dr][dc].x;
                            a += wq1[dr*3+dc] * h2[rr+dr][dc].y;
                        }
                    acc2[it][rr] += a;
                }
            }
            __syncthreads();
        }
    }

    // ---- write output ----
    #pragma unroll
    for (int it = 0; it < 2; it++) {
        int t = tid + it*256;
        int trg = t >> 6, c = t & 63;
        #pragma unroll
        for (int rr = 0; rr < 4; rr++)
            out[(size_t)b*HW + (row0 + 4*trg + rr)*WIMG + col0 + c] = acc2[it][rr] + bias2;
    }
}

// ---------------- launch ----------------
extern "C" void kernel_launch(void* const* d_in, const int* in_sizes, int n_in,
                              void* d_out, int out_size) {
    const float* x     = (const float*)d_in[0];
    const float* ref   = (const float*)d_in[1];
    const float* noise = (const float*)d_in[2];
    const float* mw1   = (const float*)d_in[3];
    const float* mb1   = (const float*)d_in[4];
    const float* mw2   = (const float*)d_in[5];
    const float* mb2   = (const float*)d_in[6];
    const float* ehw   = (const float*)d_in[7];
    const float* ehb   = (const float*)d_in[8];
    const float* fre   = (const float*)d_in[9];
    const float* wg    = (const float*)d_in[10];
    const float* wn    = (const float*)d_in[11];
    const float* ew1   = (const float*)d_in[12];
    const float* eb1   = (const float*)d_in[13];
    const float* ew2   = (const float*)d_in[14];
    const float* eb2   = (const float*)d_in[15];
    float* out = (float*)d_out;

    k_zero_scratch<<<1, 256>>>();
    k_partials<<<dim3(BATCH * CIN, 16), 256>>>(x, ref, wg, wn);
    k_gate<<<1, 16>>>(noise, mw1, mb1, mw2, mb2, ehw, ehb, fre, out, out_size);
    k_expert<<<dim3(4, 8, BATCH), 256>>>(x, ew1, eb1, ew2, eb2, out);
}